// round 9
// baseline (speedup 1.0000x reference)
#include <cuda_runtime.h>
#include <cuda_bf16.h>
#include <stdint.h>

#define NTOK 4096
#define NEDGE 131072
#define TNUM 8
#define RNUM 16
#define HNUM 8
#define BNUM 21
#define SEEDS 128
#define CAP 96            // per-row edge-list capacity (avg degree = 32, max ~66)
#define BBLK 512          // build grid: 512 blocks x 256 thr = 131072 = NEDGE

// ---------------------------------------------------------------------------
// Device scratch (.bss zero at load).
// INVARIANT across launches: g_arrive == 0 on build entry. build leaves it at
// BBLK; fill (which runs strictly after build via stream order) resets it to 0.
// No same-kernel barrier reset -> no reuse race (the R8 hang).
// ---------------------------------------------------------------------------
__device__ int g_cursor[NTOK];         // per-row raw edge count
__device__ int g_elist[NTOK * CAP];    // packed (dst << 4) | rel, per row
__device__ int g_overcnt;              // overflow edge count
__device__ int g_over[NEDGE];          // packed (src << 16) | (dst << 4) | rel
__device__ int g_arrive;               // grid-barrier arrival counter

// ---------------------------------------------------------------------------
__device__ __forceinline__ int bucketize(float dt) {
    float s  = (dt > 0.0f) ? 1.0f : ((dt < 0.0f) ? -1.0f : 0.0f);
    float sl = s * log1pf(fabsf(dt) + 1e-6f);
    float c  = fminf(fmaxf(sl, -5.0f), 5.0f);
    float norm = (c + 5.0f) / (10.0f + 1e-9f);
    int idx = (int)floorf(norm * (float)(BNUM - 1));
    idx = idx < 0 ? 0 : idx;
    idx = idx > (BNUM - 1) ? (BNUM - 1) : idx;
    return idx;
}

// ---------------------------------------------------------------------------
// Merged zero + build. All BBLK blocks co-resident (8 blocks/SM thread limit
// x 148 SMs = 1184 >= 512) -> the arrival spin cannot deadlock.
//   Phase A: zero cursors/overcnt (thread gidx zeroes cursor gidx)
//   Phase B: one-way grid barrier (arrive-and-spin; NO reset here)
//   Phase C: one-pass per-row edge-list build
// ---------------------------------------------------------------------------
__global__ __launch_bounds__(256) void build_kernel(
    const int* __restrict__ edge_src,
    const int* __restrict__ edge_dst,
    const int* __restrict__ edge_rel)
{
    const int tid  = threadIdx.x;
    const int gidx = blockIdx.x * 256 + tid;

    // Phase A: zero
    if (gidx < NTOK) g_cursor[gidx] = 0;
    if (gidx == 0)   g_overcnt = 0;
    __threadfence();           // zeros visible before any cursor atomics
    __syncthreads();

    // Phase B: one-way grid barrier (monotone counter, reset by fill_kernel)
    if (tid == 0) {
        atomicAdd(&g_arrive, 1);
        while (atomicAdd(&g_arrive, 0) < BBLK) { }
    }
    __syncthreads();

    // Phase C: build edge lists
    if (gidx < NEDGE) {
        const int s = edge_src[gidx];
        const int d = edge_dst[gidx];
        const int r = edge_rel[gidx];
        const int pos = atomicAdd(&g_cursor[s], 1);
        if (pos < CAP) {
            g_elist[s * CAP + pos] = (d << 4) | r;
        } else {
            const int o = atomicAdd(&g_overcnt, 1);
            g_over[o] = (s << 16) | (d << 4) | r;
        }
    }
}

// ---------------------------------------------------------------------------
// Fill kernel: one block per (i, h) row. Hot path byte-identical to the
// proven 81us version — NO gpu-scope fences (R5's __threadfence caused
// per-block CCTL.IVALL L1D flushes and throttled the store stream).
//   Phase 0:  block (0,0) resets g_arrive for the next launch (safe: build
//             has fully exited by stream ordering).
//   Phase 1:  direct coalesced float4 stores (~81us, ~6.6 TB/s).
//   Phase 2a: this row's edges via L2-hit atomicAdd into the fresh row.
//   Phase 2b: overflow entries (normally zero).
// ---------------------------------------------------------------------------
__global__ __launch_bounds__(256) void fill_kernel(
    const int*   __restrict__ token_type,
    const float* __restrict__ time_vec,
    const float* __restrict__ typepair_bias,  // (T, T, H)
    const float* __restrict__ temp_bias,      // (B, H)
    const float* __restrict__ adj_rel_bias,   // (R, H)
    float*       __restrict__ out)            // (H, N, N)
{
    const int i = blockIdx.x;
    const int h = blockIdx.y;
    const int tid = threadIdx.x;

    // Phase 0: restore barrier invariant for the next launch/replay
    if (i == 0 && h == 0 && tid == 0) g_arrive = 0;

    __shared__ float val8[TNUM];
    __shared__ float tb[BNUM];
    __shared__ float relb[RNUM];

    if (tid < TNUM) {
        const int tt_i = token_type[i];
        val8[tid] = typepair_bias[(tt_i * TNUM + tid) * HNUM + h];
    }
    if (tid < BNUM) tb[tid]   = temp_bias[tid * HNUM + h];
    if (tid < RNUM) relb[tid] = adj_rel_bias[tid * HNUM + h];
    __syncthreads();

    const bool  is_seed = (i < SEEDS);
    const float ti      = time_vec[i];

    float* __restrict__ orow =
        out + ((size_t)h * NTOK + (size_t)i) * (size_t)NTOK;

    // Phase 1: 4096 elements / (256 thr * 4) = 4 float4 stores per thread
    #pragma unroll
    for (int j0 = tid * 4; j0 < NTOK; j0 += 256 * 4) {
        const int4 t4 = *reinterpret_cast<const int4*>(token_type + j0);
        float4 v;
        v.x = val8[t4.x];
        v.y = val8[t4.y];
        v.z = val8[t4.z];
        v.w = val8[t4.w];
        if (is_seed) {
            const float4 tv = *reinterpret_cast<const float4*>(time_vec + j0);
            v.x += tb[bucketize(tv.x - ti)];
            v.y += tb[bucketize(tv.y - ti)];
            v.z += tb[bucketize(tv.z - ti)];
            v.w += tb[bucketize(tv.w - ti)];
        }
        *reinterpret_cast<float4*>(orow + j0) = v;
    }
    __syncthreads();   // row fully stored (visible in L2) before RMW

    // Phase 2a: this row's edges — L2-hit atomics into the fresh row
    const int count = min(g_cursor[i], CAP);
    for (int e = tid; e < count; e += 256) {
        const int p = g_elist[i * CAP + e];
        atomicAdd(orow + (p >> 4), relb[p & 15]);
    }

    // Phase 2b: overflow entries for this row (normally g_overcnt == 0)
    const int on = g_overcnt;
    for (int e = tid; e < on; e += 256) {
        const int p = g_over[e];
        if ((p >> 16) == i)
            atomicAdd(orow + ((p >> 4) & 0xFFF), relb[p & 15]);
    }
}

// ---------------------------------------------------------------------------
extern "C" void kernel_launch(void* const* d_in, const int* in_sizes, int n_in,
                              void* d_out, int out_size)
{
    const int*   token_type    = (const int*)  d_in[0];
    const int*   edge_src      = (const int*)  d_in[1];
    const int*   edge_dst      = (const int*)  d_in[2];
    const int*   edge_rel      = (const int*)  d_in[3];
    const float* time_vec      = (const float*)d_in[4];
    const float* adj_rel_bias  = (const float*)d_in[n_in - 3];
    const float* typepair_bias = (const float*)d_in[n_in - 2];
    const float* temp_bias     = (const float*)d_in[n_in - 1];
    float* out = (float*)d_out;

    build_kernel<<<BBLK, 256>>>(edge_src, edge_dst, edge_rel);

    dim3 grid_fill(NTOK, HNUM);
    fill_kernel<<<grid_fill, 256>>>(token_type, time_vec, typepair_bias,
                                    temp_bias, adj_rel_bias, out);
}

// round 10
// speedup vs baseline: 1.5242x; 1.5242x over previous
#include <cuda_runtime.h>
#include <cuda_bf16.h>
#include <stdint.h>

#define NTOK 4096
#define NEDGE 131072
#define TNUM 8
#define RNUM 16
#define HNUM 8
#define BNUM 21
#define SEEDS 128
#define CAP 96            // per-row edge-list capacity (avg degree = 32, max ~66)

// ---------------------------------------------------------------------------
// Device scratch. Zeroed by zero_kernel each launch.
// RULE (learned R5/R9): fill_kernel must NEVER write a __device__ global —
// doing so kills the read-only caching of token_type and halves fill BW.
// ---------------------------------------------------------------------------
__device__ int g_cursor[NTOK];         // per-row raw edge count
__device__ int g_elist[NTOK * CAP];    // packed (dst << 4) | rel, per row
__device__ int g_overcnt;              // overflow edge count
__device__ int g_over[NEDGE];          // packed (src << 16) | (dst << 4) | rel

// ---------------------------------------------------------------------------
__device__ __forceinline__ int bucketize(float dt) {
    float s  = (dt > 0.0f) ? 1.0f : ((dt < 0.0f) ? -1.0f : 0.0f);
    float sl = s * log1pf(fabsf(dt) + 1e-6f);
    float c  = fminf(fmaxf(sl, -5.0f), 5.0f);
    float norm = (c + 5.0f) / (10.0f + 1e-9f);
    int idx = (int)floorf(norm * (float)(BNUM - 1));
    idx = idx < 0 ? 0 : idx;
    idx = idx > (BNUM - 1) ? (BNUM - 1) : idx;
    return idx;
}

// ---------------------------------------------------------------------------
// Zero cursors + overflow counter. Triggers PDL completion immediately so the
// dependent build kernel can begin launching; build waits for our writes via
// cudaGridDependencySynchronize before its atomics.
// ---------------------------------------------------------------------------
__global__ __launch_bounds__(256) void zero_kernel() {
    cudaTriggerProgrammaticLaunchCompletion();
    int i = blockIdx.x * blockDim.x + threadIdx.x;
    if (i < NTOK) g_cursor[i] = 0;
    if (i == 0)   g_overcnt = 0;
}

// ---------------------------------------------------------------------------
// One-pass per-row edge-list build (PDL-launched over zero_kernel).
// Edge loads proceed immediately; the grid-dependency wait sits between the
// loads and the cursor atomics.
// ---------------------------------------------------------------------------
__global__ __launch_bounds__(256) void build_kernel(
    const int* __restrict__ edge_src,
    const int* __restrict__ edge_dst,
    const int* __restrict__ edge_rel)
{
    cudaTriggerProgrammaticLaunchCompletion();   // let fill start launching
    int e = blockIdx.x * blockDim.x + threadIdx.x;
    int s = 0, d = 0, r = 0;
    if (e < NEDGE) {
        s = edge_src[e];
        d = edge_dst[e];
        r = edge_rel[e];
    }
    cudaGridDependencySynchronize();             // zero_kernel writes visible
    if (e < NEDGE) {
        int pos = atomicAdd(&g_cursor[s], 1);
        if (pos < CAP) {
            g_elist[s * CAP + pos] = (d << 4) | r;
        } else {
            int o = atomicAdd(&g_overcnt, 1);
            g_over[o] = (s << 16) | (d << 4) | r;
        }
    }
}

// ---------------------------------------------------------------------------
// Fill kernel (PDL-launched over build_kernel): one block per (i, h) row.
// Reads ONLY — no stores to device globals (R5/R9 lesson). Phase 1 is fully
// independent of build; the grid-dependency wait sits after the hot loop, so
// build+zero hide entirely under the ~80us store stream.
//   Phase 1:  direct coalesced float4 stores (~81us, ~6.6 TB/s).
//   Phase 2a: this row's edges via L2-hit atomicAdd into the fresh row.
//   Phase 2b: overflow entries (normally zero).
// ---------------------------------------------------------------------------
__global__ __launch_bounds__(256) void fill_kernel(
    const int*   __restrict__ token_type,
    const float* __restrict__ time_vec,
    const float* __restrict__ typepair_bias,  // (T, T, H)
    const float* __restrict__ temp_bias,      // (B, H)
    const float* __restrict__ adj_rel_bias,   // (R, H)
    float*       __restrict__ out)            // (H, N, N)
{
    const int i = blockIdx.x;
    const int h = blockIdx.y;
    const int tid = threadIdx.x;

    __shared__ float val8[TNUM];
    __shared__ float tb[BNUM];
    __shared__ float relb[RNUM];

    if (tid < TNUM) {
        const int tt_i = token_type[i];
        val8[tid] = typepair_bias[(tt_i * TNUM + tid) * HNUM + h];
    }
    if (tid < BNUM) tb[tid]   = temp_bias[tid * HNUM + h];
    if (tid < RNUM) relb[tid] = adj_rel_bias[tid * HNUM + h];
    __syncthreads();

    const bool  is_seed = (i < SEEDS);
    const float ti      = time_vec[i];

    float* __restrict__ orow =
        out + ((size_t)h * NTOK + (size_t)i) * (size_t)NTOK;

    // Phase 1: 4096 elements / (256 thr * 4) = 4 float4 stores per thread
    #pragma unroll
    for (int j0 = tid * 4; j0 < NTOK; j0 += 256 * 4) {
        const int4 t4 = *reinterpret_cast<const int4*>(token_type + j0);
        float4 v;
        v.x = val8[t4.x];
        v.y = val8[t4.y];
        v.z = val8[t4.z];
        v.w = val8[t4.w];
        if (is_seed) {
            const float4 tv = *reinterpret_cast<const float4*>(time_vec + j0);
            v.x += tb[bucketize(tv.x - ti)];
            v.y += tb[bucketize(tv.y - ti)];
            v.z += tb[bucketize(tv.z - ti)];
            v.w += tb[bucketize(tv.w - ti)];
        }
        *reinterpret_cast<float4*>(orow + j0) = v;
    }
    __syncthreads();               // row fully stored before RMW

    cudaGridDependencySynchronize();   // build's cursors/lists now visible

    // Phase 2a: this row's edges — L2-hit atomics into the fresh row
    const int count = min(g_cursor[i], CAP);
    for (int e = tid; e < count; e += 256) {
        const int p = g_elist[i * CAP + e];
        atomicAdd(orow + (p >> 4), relb[p & 15]);
    }

    // Phase 2b: overflow entries for this row (normally g_overcnt == 0)
    const int on = g_overcnt;
    for (int e = tid; e < on; e += 256) {
        const int p = g_over[e];
        if ((p >> 16) == i)
            atomicAdd(orow + ((p >> 4) & 0xFFF), relb[p & 15]);
    }
}

// ---------------------------------------------------------------------------
// Launch with PDL edges: zero -> build -> fill overlap; only zero's launch
// latency stays exposed.
// ---------------------------------------------------------------------------
extern "C" void kernel_launch(void* const* d_in, const int* in_sizes, int n_in,
                              void* d_out, int out_size)
{
    const int*   token_type    = (const int*)  d_in[0];
    const int*   edge_src      = (const int*)  d_in[1];
    const int*   edge_dst      = (const int*)  d_in[2];
    const int*   edge_rel      = (const int*)  d_in[3];
    const float* time_vec      = (const float*)d_in[4];
    const float* adj_rel_bias  = (const float*)d_in[n_in - 3];
    const float* typepair_bias = (const float*)d_in[n_in - 2];
    const float* temp_bias     = (const float*)d_in[n_in - 1];
    float* out = (float*)d_out;

    cudaLaunchAttribute pdl[1];
    pdl[0].id = cudaLaunchAttributeProgrammaticStreamSerialization;
    pdl[0].val.programmaticStreamSerializationAllowed = 1;

    // zero: plain launch
    zero_kernel<<<(NTOK + 255) / 256, 256>>>();

    // build: PDL over zero
    {
        cudaLaunchConfig_t cfg = {};
        cfg.gridDim  = dim3((NEDGE + 255) / 256);
        cfg.blockDim = dim3(256);
        cfg.attrs    = pdl;
        cfg.numAttrs = 1;
        cfg.stream   = 0;
        cudaLaunchKernelEx(&cfg, build_kernel, edge_src, edge_dst, edge_rel);
    }

    // fill: PDL over build
    {
        cudaLaunchConfig_t cfg = {};
        cfg.gridDim  = dim3(NTOK, HNUM);
        cfg.blockDim = dim3(256);
        cfg.attrs    = pdl;
        cfg.numAttrs = 1;
        cfg.stream   = 0;
        cudaLaunchKernelEx(&cfg, fill_kernel, token_type, time_vec,
                           typepair_bias, temp_bias, adj_rel_bias, out);
    }
}